// round 2
// baseline (speedup 1.0000x reference)
#include <cuda_runtime.h>
#include <cuda_bf16.h>

// ContrastiveLoss: N=8192, D=256, 64 classes, TEMPERATURE=0.5, fp32 in/out.
//
// loss = sum_i [ P_i*(2 + log denom_i) - possum_i ] / n_pos
//   denom_i  = sum_{j!=i} exp(sim_ij - 2)      (shift-invariant; sim<=2 since unit-norm)
//   possum_i = sum_{j: lab_j==lab_i, j!=i} sim_ij
//   P_i      = count[lab_i] - 1,  n_pos = sum_c count_c*(count_c-1)

#define N_ROWS 8192
#define DIM    256
#define NCLS   64

__device__ float g_denom[N_ROWS];
__device__ float g_pos[N_ROWS];

// ---- label width detection: int64 labels (<64) have zero high words ----
__device__ __forceinline__ int detect_is64(const int* L) {
    int s = 0;
#pragma unroll
    for (int k = 0; k < 64; k++) s |= L[2 * k + 1];
    return (s == 0) ? 1 : 0;
}
__device__ __forceinline__ int get_label(const int* L, int i, int is64) {
    return is64 ? L[2 * i] : L[i];
}

__global__ void zero_kernel() {
    int i = blockIdx.x * blockDim.x + threadIdx.x;
    if (i < N_ROWS) { g_denom[i] = 0.f; g_pos[i] = 0.f; }
}

// ---- main fused GEMM + softmax-denominator epilogue ----
// BM=BN=128, BK=32, 256 threads, 8x8 micro-tile per thread.
__global__ __launch_bounds__(256, 2)
void sim_kernel(const float* __restrict__ E, const int* __restrict__ Lraw) {
    __shared__ float As[32][128];
    __shared__ float Bs[32][128];
    __shared__ int   labI[128], labJ[128];
    __shared__ float redD[128], redP[128];
    __shared__ int   s_is64;

    const int bi = blockIdx.y, bj = blockIdx.x;
    const int row0 = bi * 128, col0 = bj * 128;
    const int tid = threadIdx.x;
    const int ty = tid >> 4, tx = tid & 15;

    if (tid == 0) s_is64 = detect_is64(Lraw);
    __syncthreads();
    const int is64 = s_is64;

    if (tid < 128) {
        labI[tid] = get_label(Lraw, row0 + tid, is64);
        labJ[tid] = get_label(Lraw, col0 + tid, is64);
        redD[tid] = 0.f;
        redP[tid] = 0.f;
    }

    float acc[8][8];
#pragma unroll
    for (int r = 0; r < 8; r++)
#pragma unroll
        for (int c = 0; c < 8; c++) acc[r][c] = 0.f;

    for (int k0 = 0; k0 < DIM; k0 += 32) {
        // load 128x32 A-tile and B-tile (both slices of E), transposed to [k][m]
#pragma unroll
        for (int l = 0; l < 4; l++) {
            int idx = tid + l * 256;
            int m  = idx >> 3;
            int c4 = (idx & 7) << 2;
            float4 va = *(const float4*)(E + (size_t)(row0 + m) * DIM + k0 + c4);
            As[c4 + 0][m] = va.x; As[c4 + 1][m] = va.y;
            As[c4 + 2][m] = va.z; As[c4 + 3][m] = va.w;
            float4 vb = *(const float4*)(E + (size_t)(col0 + m) * DIM + k0 + c4);
            Bs[c4 + 0][m] = vb.x; Bs[c4 + 1][m] = vb.y;
            Bs[c4 + 2][m] = vb.z; Bs[c4 + 3][m] = vb.w;
        }
        __syncthreads();
#pragma unroll 8
        for (int k = 0; k < 32; k++) {
            float a[8], b[8];
            *(float4*)(a)     = *(const float4*)&As[k][ty * 8];
            *(float4*)(a + 4) = *(const float4*)&As[k][ty * 8 + 4];
            *(float4*)(b)     = *(const float4*)&Bs[k][tx * 8];
            *(float4*)(b + 4) = *(const float4*)&Bs[k][tx * 8 + 4];
#pragma unroll
            for (int r = 0; r < 8; r++)
#pragma unroll
                for (int c = 0; c < 8; c++) acc[r][c] = fmaf(a[r], b[c], acc[r][c]);
        }
        __syncthreads();
    }

    // epilogue: per-row denom / positive-sum partials
#pragma unroll
    for (int r = 0; r < 8; r++) {
        const int i_loc = ty * 8 + r;
        const int gi = row0 + i_loc;
        const int li = labI[i_loc];
        float dsum = 0.f, psum = 0.f;
#pragma unroll
        for (int c = 0; c < 8; c++) {
            const int j_loc = tx * 8 + c;
            const int gj = col0 + j_loc;
            const float s = 2.0f * acc[r][c];       // /TEMPERATURE
            const float e = __expf(s - 2.0f);
            if (gj != gi) {
                dsum += e;
                if (labJ[j_loc] == li) psum += s;
            }
        }
        atomicAdd(&redD[i_loc], dsum);
        atomicAdd(&redP[i_loc], psum);
    }
    __syncthreads();
    if (tid < 128) {
        atomicAdd(&g_denom[row0 + tid], redD[tid]);
        atomicAdd(&g_pos[row0 + tid],   redP[tid]);
    }
}

// ---- finalize: label histogram, per-row combine, scalar loss ----
__global__ void finalize_kernel(const int* __restrict__ Lraw, float* __restrict__ out) {
    __shared__ int cnt[NCLS];
    __shared__ double red[256];
    __shared__ int s_is64;
    const int tid = threadIdx.x;

    if (tid == 0) s_is64 = detect_is64(Lraw);
    if (tid < NCLS) cnt[tid] = 0;
    __syncthreads();
    const int is64 = s_is64;

    for (int i = tid; i < N_ROWS; i += 256)
        atomicAdd(&cnt[get_label(Lraw, i, is64)], 1);
    __syncthreads();

    double acc = 0.0;
    for (int i = tid; i < N_ROWS; i += 256) {
        int P = cnt[get_label(Lraw, i, is64)] - 1;
        acc += (double)P * (2.0 + (double)logf(g_denom[i])) - (double)g_pos[i];
    }
    red[tid] = acc;
    __syncthreads();
    for (int s = 128; s > 0; s >>= 1) {
        if (tid < s) red[tid] += red[tid + s];
        __syncthreads();
    }
    if (tid == 0) {
        long long npos = 0;
        for (int c = 0; c < NCLS; c++)
            npos += (long long)cnt[c] * (long long)(cnt[c] - 1);
        out[0] = (float)(red[0] / (double)npos);
    }
}

extern "C" void kernel_launch(void* const* d_in, const int* in_sizes, int n_in,
                              void* d_out, int out_size) {
    const float* E    = (const float*)d_in[0];
    const int*   Lraw = (const int*)d_in[1];   // width auto-detected on device
    float* out = (float*)d_out;

    zero_kernel<<<(N_ROWS + 255) / 256, 256>>>();
    dim3 grid(N_ROWS / 128, N_ROWS / 128);
    sim_kernel<<<grid, 256>>>(E, Lraw);
    finalize_kernel<<<1, 256>>>(Lraw, out);
}

// round 4
// speedup vs baseline: 6.9672x; 6.9672x over previous
#include <cuda_runtime.h>
#include <cuda_bf16.h>
#include <cstdint>

// ContrastiveLoss: N=8192, D=256, 64 classes, T=0.5.
// loss = sum_i [ P_i*(2 + log denom_i) - possum_i ] / n_pos
//   denom_i  = sum_{j!=i} exp(sim_ij - 2)   (shift-invariant; sim<=2, unit-norm)
//   possum_i = sum_{j: lab_j==lab_i, j!=i} sim_ij
// GEMM sim = E@E^T via mma.sync bf16 (portable HMMA; tcgen05 rejected by
// harness toolchain which emits compute_103 PTX, not sm_103a).

#define N_ROWS 8192
#define DIM    256
#define NCLS   64
#define BM     128
#define BN     128
#define KCHUNK 64
#define NCHUNK (DIM / KCHUNK)          // 4
#define SSTRIDE 72                     // bf16 elems per smem row (64 + 8 pad)

__device__ float g_denom[N_ROWS];
__device__ float g_pos[N_ROWS];
__device__ __nv_bfloat16 g_Ebf[N_ROWS * DIM];

__device__ __forceinline__ uint32_t smem_u32(const void* p) {
    uint32_t a;
    asm("{ .reg .u64 t; cvta.to.shared.u64 t, %1; cvt.u32.u64 %0, t; }" : "=r"(a) : "l"(p));
    return a;
}
__device__ __forceinline__ void ldsm_x4(uint32_t& r0, uint32_t& r1, uint32_t& r2, uint32_t& r3,
                                        uint32_t addr) {
    asm volatile("ldmatrix.sync.aligned.m8n8.x4.shared.b16 {%0,%1,%2,%3}, [%4];"
                 : "=r"(r0), "=r"(r1), "=r"(r2), "=r"(r3) : "r"(addr));
}
__device__ __forceinline__ void mma16816(float* d, const uint32_t* a, uint32_t b0, uint32_t b1) {
    asm volatile(
        "mma.sync.aligned.m16n8k16.row.col.f32.bf16.bf16.f32 "
        "{%0,%1,%2,%3}, {%4,%5,%6,%7}, {%8,%9}, {%0,%1,%2,%3};"
        : "+f"(d[0]), "+f"(d[1]), "+f"(d[2]), "+f"(d[3])
        : "r"(a[0]), "r"(a[1]), "r"(a[2]), "r"(a[3]), "r"(b0), "r"(b1));
}
#define CP_ASYNC16(sm, gp) asm volatile("cp.async.cg.shared.global [%0], [%1], 16;" :: "r"(sm), "l"(gp) : "memory")
#define CP_COMMIT()        asm volatile("cp.async.commit_group;" ::: "memory")
#define CP_WAIT(n)         asm volatile("cp.async.wait_group %0;" :: "n"(n) : "memory")

// ---- label width detection: int64 labels (<64) have zero high words ----
__device__ __forceinline__ int detect_is64(const int* L) {
    int s = 0;
#pragma unroll
    for (int k = 0; k < 64; k++) s |= L[2 * k + 1];
    return (s == 0) ? 1 : 0;
}
__device__ __forceinline__ int get_label(const int* L, int i, int is64) {
    return is64 ? L[2 * i] : L[i];
}

// ---- prep: zero accumulators + convert E to bf16 ----
__global__ void prep_kernel(const float* __restrict__ E) {
    int i = blockIdx.x * blockDim.x + threadIdx.x;   // one float4 per thread
    if (i < N_ROWS) { g_denom[i] = 0.f; g_pos[i] = 0.f; }
    float4 v = ((const float4*)E)[i];
    __nv_bfloat162 p0 = __floats2bfloat162_rn(v.x, v.y);
    __nv_bfloat162 p1 = __floats2bfloat162_rn(v.z, v.w);
    uint2 o;
    o.x = *(uint32_t*)&p0;
    o.y = *(uint32_t*)&p1;
    ((uint2*)g_Ebf)[i] = o;
}

// ---- fused HMMA GEMM + epilogue ----
// 256 threads = 8 warps in 2(m) x 4(n); warp tile 64x32; thread acc 64 fp32.
__global__ __launch_bounds__(256, 2)
void sim_kernel(const int* __restrict__ Lraw) {
    extern __shared__ __nv_bfloat16 smem[];   // [2 stages][A 128*72 | B 128*72]
    __shared__ int   labI[BM], labJ[BN];
    __shared__ float redD[BM], redP[BM];
    __shared__ int   s_is64;

    const int tid  = threadIdx.x;
    const int wid  = tid >> 5, lane = tid & 31;
    const int wm   = wid >> 2, wn = wid & 3;          // warp coords
    const int row0 = blockIdx.y * BM, col0 = blockIdx.x * BN;

    const uint32_t sbase = smem_u32(smem);
    const uint32_t stageBytes = 2u * 2u * BM * SSTRIDE;     // A+B one stage (bytes)

    if (tid == 0) s_is64 = detect_is64(Lraw);
    if (tid < BM) { redD[tid] = 0.f; redP[tid] = 0.f; }

    // ---- async tile loader: chunk c (k = c*KCHUNK), stage s ----
    auto load_chunk = [&](int c, int s) {
        const __nv_bfloat16* gA = g_Ebf + (size_t)row0 * DIM + c * KCHUNK;
        const __nv_bfloat16* gB = g_Ebf + (size_t)col0 * DIM + c * KCHUNK;
        uint32_t stA = sbase + s * stageBytes;
        uint32_t stB = stA + 2u * BM * SSTRIDE;
#pragma unroll
        for (int t = 0; t < 4; t++) {
            int idx = tid + t * 256;               // 0..1023 16B units
            int r = idx >> 3, c16 = idx & 7;
            uint32_t so = (uint32_t)(r * SSTRIDE + c16 * 8) * 2u;
            CP_ASYNC16(stA + so, gA + (size_t)r * DIM + c16 * 8);
            CP_ASYNC16(stB + so, gB + (size_t)r * DIM + c16 * 8);
        }
    };

    float acc[4][4][4];
#pragma unroll
    for (int mf = 0; mf < 4; mf++)
#pragma unroll
        for (int nf = 0; nf < 4; nf++)
#pragma unroll
            for (int e = 0; e < 4; e++) acc[mf][nf][e] = 0.f;

    load_chunk(0, 0);
    CP_COMMIT();

    if (tid < BM) labI[tid] = get_label(Lraw, row0 + tid, s_is64);
    else if (tid < BM + BN) labJ[tid - BM] = get_label(Lraw, col0 + tid - BM, s_is64);

    // precomputed fragment address offsets (within a stage)
    const uint32_t aRow = (uint32_t)(wm * 64 + (lane & 15));
    const uint32_t aKof = (uint32_t)((lane >> 4) * 8);
    const uint32_t bRow = (uint32_t)(wn * 32 + (lane & 7) + ((lane >> 4) << 3));
    const uint32_t bKof = (uint32_t)(((lane >> 3) & 1) * 8);

    for (int c = 0; c < NCHUNK; c++) {
        if (c + 1 < NCHUNK) {
            load_chunk(c + 1, (c + 1) & 1);
            CP_COMMIT();
            CP_WAIT(1);
        } else {
            CP_WAIT(0);
        }
        __syncthreads();

        uint32_t stA = sbase + (c & 1) * stageBytes;
        uint32_t stB = stA + 2u * BM * SSTRIDE;
#pragma unroll
        for (int k16 = 0; k16 < KCHUNK / 16; k16++) {
            const uint32_t k0 = k16 * 16;
            uint32_t a[4][4], b[2][4];
#pragma unroll
            for (int mf = 0; mf < 4; mf++)
                ldsm_x4(a[mf][0], a[mf][1], a[mf][2], a[mf][3],
                        stA + ((aRow + mf * 16) * SSTRIDE + k0 + aKof) * 2u);
#pragma unroll
            for (int nf2 = 0; nf2 < 2; nf2++)
                ldsm_x4(b[nf2][0], b[nf2][1], b[nf2][2], b[nf2][3],
                        stB + ((bRow + nf2 * 16) * SSTRIDE + k0 + bKof) * 2u);
#pragma unroll
            for (int mf = 0; mf < 4; mf++)
#pragma unroll
                for (int nf = 0; nf < 4; nf++)
                    mma16816(acc[mf][nf], a[mf], b[nf >> 1][(nf & 1) * 2],
                             b[nf >> 1][(nf & 1) * 2 + 1]);
        }
        __syncthreads();
    }

    // ---- epilogue: exp + masked sums, lane-group reduce, smem atomics ----
#pragma unroll
    for (int mf = 0; mf < 4; mf++) {
#pragma unroll
        for (int h = 0; h < 2; h++) {
            const int rloc = wm * 64 + mf * 16 + (lane >> 2) + 8 * h;
            const int gi = row0 + rloc;
            const int li = labI[rloc];
            float dsum = 0.f, psum = 0.f;
#pragma unroll
            for (int nf = 0; nf < 4; nf++) {
#pragma unroll
                for (int e = 0; e < 2; e++) {
                    const int cloc = wn * 32 + nf * 8 + 2 * (lane & 3) + e;
                    const int gj = col0 + cloc;
                    const float s = 2.0f * acc[mf][nf][h * 2 + e];   // /TEMPERATURE
                    const float ex = __expf(s - 2.0f);
                    if (gj != gi) {
                        dsum += ex;
                        if (labJ[cloc] == li) psum += s;
                    }
                }
            }
            dsum += __shfl_xor_sync(0xFFFFFFFF, dsum, 1);
            dsum += __shfl_xor_sync(0xFFFFFFFF, dsum, 2);
            psum += __shfl_xor_sync(0xFFFFFFFF, psum, 1);
            psum += __shfl_xor_sync(0xFFFFFFFF, psum, 2);
            if ((lane & 3) == 0) {
                atomicAdd(&redD[rloc], dsum);
                atomicAdd(&redP[rloc], psum);
            }
        }
    }
    __syncthreads();
    if (tid < BM) {
        atomicAdd(&g_denom[row0 + tid], redD[tid]);
        atomicAdd(&g_pos[row0 + tid],   redP[tid]);
    }
}

// ---- finalize: label histogram, per-row combine, scalar loss ----
__global__ void finalize_kernel(const int* __restrict__ Lraw, float* __restrict__ out) {
    __shared__ int cnt[NCLS];
    __shared__ double red[256];
    __shared__ int s_is64;
    const int tid = threadIdx.x;

    if (tid == 0) s_is64 = detect_is64(Lraw);
    if (tid < NCLS) cnt[tid] = 0;
    __syncthreads();
    const int is64 = s_is64;

    for (int i = tid; i < N_ROWS; i += 256)
        atomicAdd(&cnt[get_label(Lraw, i, is64)], 1);
    __syncthreads();

    double acc = 0.0;
    for (int i = tid; i < N_ROWS; i += 256) {
        int P = cnt[get_label(Lraw, i, is64)] - 1;
        acc += (double)P * (2.0 + (double)logf(g_denom[i])) - (double)g_pos[i];
    }
    red[tid] = acc;
    __syncthreads();
    for (int s = 128; s > 0; s >>= 1) {
        if (tid < s) red[tid] += red[tid + s];
        __syncthreads();
    }
    if (tid == 0) {
        long long npos = 0;
        for (int c = 0; c < NCLS; c++)
            npos += (long long)cnt[c] * (long long)(cnt[c] - 1);
        out[0] = (float)(red[0] / (double)npos);
    }
}

extern "C" void kernel_launch(void* const* d_in, const int* in_sizes, int n_in,
                              void* d_out, int out_size) {
    const float* E    = (const float*)d_in[0];
    const int*   Lraw = (const int*)d_in[1];   // width auto-detected on device
    float* out = (float*)d_out;

    const int DYN_SMEM = 2 * 2 * 2 * BM * SSTRIDE;   // 2 stages * (A+B) * bytes = 73728
    cudaFuncSetAttribute(sim_kernel, cudaFuncAttributeMaxDynamicSharedMemorySize, DYN_SMEM);

    prep_kernel<<<(N_ROWS * DIM / 4) / 256, 256>>>(E);
    dim3 grid(N_ROWS / BN, N_ROWS / BM);
    sim_kernel<<<grid, 256, DYN_SMEM>>>(Lraw);
    finalize_kernel<<<1, 256>>>(Lraw, out);
}

// round 5
// speedup vs baseline: 9.3206x; 1.3378x over previous
#include <cuda_runtime.h>
#include <cuda_bf16.h>
#include <cstdint>

// ContrastiveLoss: N=8192, D=256, 64 classes, T=0.5.
// loss = sum_i [ P_i*(2 + log denom_i) - possum_i ] / n_pos
//   denom_i  = sum_{j!=i} exp(sim_ij - 2)   (shift-invariant; sim<=2, unit-norm)
//   possum_i = sum_{j: lab_j==lab_i, j!=i} sim_ij
// sim = E@E^T via bf16 mma.sync; SYMMETRIC: only upper-triangular tiles are
// computed, off-diagonal tiles feed both row-block and column-block stats.

#define N_ROWS 8192
#define DIM    256
#define NCLS   64
#define BM     128
#define BN     128
#define KCHUNK 64
#define NCHUNK (DIM / KCHUNK)          // 4
#define SSTRIDE 72                     // bf16 elems per smem row (64 + 8 pad)
#define NB     (N_ROWS / BM)           // 64 tile-blocks per side
#define NTILES (NB * (NB + 1) / 2)     // 2080 upper-tri tiles

__device__ float g_denom[N_ROWS];
__device__ float g_pos[N_ROWS];
__device__ __nv_bfloat16 g_Ebf[N_ROWS * DIM];

__device__ __forceinline__ uint32_t smem_u32(const void* p) {
    uint32_t a;
    asm("{ .reg .u64 t; cvta.to.shared.u64 t, %1; cvt.u32.u64 %0, t; }" : "=r"(a) : "l"(p));
    return a;
}
__device__ __forceinline__ void ldsm_x4(uint32_t& r0, uint32_t& r1, uint32_t& r2, uint32_t& r3,
                                        uint32_t addr) {
    asm volatile("ldmatrix.sync.aligned.m8n8.x4.shared.b16 {%0,%1,%2,%3}, [%4];"
                 : "=r"(r0), "=r"(r1), "=r"(r2), "=r"(r3) : "r"(addr));
}
__device__ __forceinline__ void mma16816(float* d, const uint32_t* a, uint32_t b0, uint32_t b1) {
    asm volatile(
        "mma.sync.aligned.m16n8k16.row.col.f32.bf16.bf16.f32 "
        "{%0,%1,%2,%3}, {%4,%5,%6,%7}, {%8,%9}, {%0,%1,%2,%3};"
        : "+f"(d[0]), "+f"(d[1]), "+f"(d[2]), "+f"(d[3])
        : "r"(a[0]), "r"(a[1]), "r"(a[2]), "r"(a[3]), "r"(b0), "r"(b1));
}
#define CP_ASYNC16(sm, gp) asm volatile("cp.async.cg.shared.global [%0], [%1], 16;" :: "r"(sm), "l"(gp) : "memory")
#define CP_COMMIT()        asm volatile("cp.async.commit_group;" ::: "memory")
#define CP_WAIT(n)         asm volatile("cp.async.wait_group %0;" :: "n"(n) : "memory")

// ---- label width detection: int64 labels (<64) have zero high words ----
__device__ __forceinline__ int detect_is64(const int* L) {
    int s = 0;
#pragma unroll
    for (int k = 0; k < 64; k++) s |= L[2 * k + 1];
    return (s == 0) ? 1 : 0;
}
__device__ __forceinline__ int get_label(const int* L, int i, int is64) {
    return is64 ? L[2 * i] : L[i];
}

// ---- prep: zero accumulators + convert E to bf16 ----
__global__ void prep_kernel(const float* __restrict__ E) {
    int i = blockIdx.x * blockDim.x + threadIdx.x;   // one float4 per thread
    if (i < N_ROWS) { g_denom[i] = 0.f; g_pos[i] = 0.f; }
    float4 v = ((const float4*)E)[i];
    __nv_bfloat162 p0 = __floats2bfloat162_rn(v.x, v.y);
    __nv_bfloat162 p1 = __floats2bfloat162_rn(v.z, v.w);
    uint2 o;
    o.x = *(uint32_t*)&p0;
    o.y = *(uint32_t*)&p1;
    ((uint2*)g_Ebf)[i] = o;
}

// ---- fused HMMA GEMM + dual (row+col) epilogue, upper-tri tiles ----
// 256 threads = 8 warps in 2(m) x 4(n); warp tile 64x32; thread acc 64 fp32.
__global__ __launch_bounds__(256, 2)
void sim_kernel(const int* __restrict__ Lraw) {
    extern __shared__ __nv_bfloat16 smem[];   // [2 stages][A 128*72 | B 128*72]
    __shared__ int   labI[BM], labJ[BN];
    __shared__ float redD[BM], redP[BM];      // row-block partials
    __shared__ float redDc[BN], redPc[BN];    // col-block partials
    __shared__ int   s_is64;

    const int tid  = threadIdx.x;
    const int wid  = tid >> 5, lane = tid & 31;
    const int wm   = wid >> 2, wn = wid & 3;          // warp coords

    // ---- linear tile id -> upper-triangular (bi, bj) ----
    const int t = blockIdx.x;
    int bi = (int)((2.0f * NB + 1.0f -
                    sqrtf((2.0f * NB + 1.0f) * (2.0f * NB + 1.0f) - 8.0f * (float)t)) * 0.5f);
    // offset(b) = b*NB - b*(b-1)/2 ; correct rounding
    while (bi > 0 && bi * NB - bi * (bi - 1) / 2 > t) bi--;
    while ((bi + 1) * NB - (bi + 1) * bi / 2 <= t) bi++;
    const int bj = bi + (t - (bi * NB - bi * (bi - 1) / 2));
    const int row0 = bi * BM, col0 = bj * BN;
    const bool offdiag = (bi != bj);

    const uint32_t sbase = smem_u32(smem);
    const uint32_t stageBytes = 2u * 2u * BM * SSTRIDE;     // A+B one stage (bytes)

    if (tid == 0) s_is64 = detect_is64(Lraw);
    if (tid < BM) { redD[tid] = 0.f; redP[tid] = 0.f; redDc[tid] = 0.f; redPc[tid] = 0.f; }

    // ---- async tile loader: chunk c (k = c*KCHUNK), stage s ----
    auto load_chunk = [&](int c, int s) {
        const __nv_bfloat16* gA = g_Ebf + (size_t)row0 * DIM + c * KCHUNK;
        const __nv_bfloat16* gB = g_Ebf + (size_t)col0 * DIM + c * KCHUNK;
        uint32_t stA = sbase + s * stageBytes;
        uint32_t stB = stA + 2u * BM * SSTRIDE;
#pragma unroll
        for (int u = 0; u < 4; u++) {
            int idx = tid + u * 256;               // 0..1023 16B units
            int r = idx >> 3, c16 = idx & 7;
            uint32_t so = (uint32_t)(r * SSTRIDE + c16 * 8) * 2u;
            CP_ASYNC16(stA + so, gA + (size_t)r * DIM + c16 * 8);
            CP_ASYNC16(stB + so, gB + (size_t)r * DIM + c16 * 8);
        }
    };

    float acc[4][4][4];
#pragma unroll
    for (int mf = 0; mf < 4; mf++)
#pragma unroll
        for (int nf = 0; nf < 4; nf++)
#pragma unroll
            for (int e = 0; e < 4; e++) acc[mf][nf][e] = 0.f;

    load_chunk(0, 0);
    CP_COMMIT();
    __syncthreads();                         // publishes s_is64 (and red* zeros)

    if (tid < BM) labI[tid] = get_label(Lraw, row0 + tid, s_is64);
    else if (tid < BM + BN) labJ[tid - BM] = get_label(Lraw, col0 + tid - BM, s_is64);

    // fragment address components (within a stage)
    const uint32_t aRow = (uint32_t)(wm * 64 + (lane & 15));
    const uint32_t aKof = (uint32_t)((lane >> 4) * 8);
    const uint32_t bRow = (uint32_t)(wn * 32 + (lane & 7) + ((lane >> 4) << 3));
    const uint32_t bKof = (uint32_t)(((lane >> 3) & 1) * 8);

    for (int c = 0; c < NCHUNK; c++) {
        if (c + 1 < NCHUNK) {
            load_chunk(c + 1, (c + 1) & 1);
            CP_COMMIT();
            CP_WAIT(1);
        } else {
            CP_WAIT(0);
        }
        __syncthreads();

        uint32_t stA = sbase + (c & 1) * stageBytes;
        uint32_t stB = stA + 2u * BM * SSTRIDE;
#pragma unroll
        for (int k16 = 0; k16 < KCHUNK / 16; k16++) {
            const uint32_t k0 = k16 * 16;
            uint32_t a[4][4], b[2][4];
#pragma unroll
            for (int mf = 0; mf < 4; mf++)
                ldsm_x4(a[mf][0], a[mf][1], a[mf][2], a[mf][3],
                        stA + ((aRow + mf * 16) * SSTRIDE + k0 + aKof) * 2u);
#pragma unroll
            for (int nf2 = 0; nf2 < 2; nf2++)
                ldsm_x4(b[nf2][0], b[nf2][1], b[nf2][2], b[nf2][3],
                        stB + ((bRow + nf2 * 16) * SSTRIDE + k0 + bKof) * 2u);
#pragma unroll
            for (int mf = 0; mf < 4; mf++)
#pragma unroll
                for (int nf = 0; nf < 4; nf++)
                    mma16816(acc[mf][nf], a[mf], b[nf >> 1][(nf & 1) * 2],
                             b[nf >> 1][(nf & 1) * 2 + 1]);
        }
        __syncthreads();
    }

    // ---- row epilogue: exp + masked sums, lane-group reduce (xor 1,2) ----
#pragma unroll
    for (int mf = 0; mf < 4; mf++) {
#pragma unroll
        for (int h = 0; h < 2; h++) {
            const int rloc = wm * 64 + mf * 16 + (lane >> 2) + 8 * h;
            const int gi = row0 + rloc;
            const int li = labI[rloc];
            float dsum = 0.f, psum = 0.f;
#pragma unroll
            for (int nf = 0; nf < 4; nf++) {
#pragma unroll
                for (int e = 0; e < 2; e++) {
                    const int cloc = wn * 32 + nf * 8 + 2 * (lane & 3) + e;
                    const int gj = col0 + cloc;
                    const float s = 2.0f * acc[mf][nf][h * 2 + e];   // /TEMPERATURE
                    const float ex = __expf(s - 2.0f);
                    if (gj != gi) {                                  // only diag tiles hit
                        dsum += ex;
                        if (labJ[cloc] == li) psum += s;
                    }
                }
            }
            dsum += __shfl_xor_sync(0xFFFFFFFF, dsum, 1);
            dsum += __shfl_xor_sync(0xFFFFFFFF, dsum, 2);
            psum += __shfl_xor_sync(0xFFFFFFFF, psum, 1);
            psum += __shfl_xor_sync(0xFFFFFFFF, psum, 2);
            if ((lane & 3) == 0) {
                atomicAdd(&redD[rloc], dsum);
                atomicAdd(&redP[rloc], psum);
            }
        }
    }

    // ---- col epilogue (off-diagonal tiles only): symmetric contributions ----
    if (offdiag) {
#pragma unroll
        for (int nf = 0; nf < 4; nf++) {
#pragma unroll
            for (int e = 0; e < 2; e++) {
                const int cloc = wn * 32 + nf * 8 + 2 * (lane & 3) + e;
                const int lj = labJ[cloc];
                float dsum = 0.f, psum = 0.f;
#pragma unroll
                for (int mf = 0; mf < 4; mf++) {
#pragma unroll
                    for (int h = 0; h < 2; h++) {
                        const int rloc = wm * 64 + mf * 16 + (lane >> 2) + 8 * h;
                        const float s = 2.0f * acc[mf][nf][h * 2 + e];
                        dsum += __expf(s - 2.0f);
                        if (labI[rloc] == lj) psum += s;
                    }
                }
                dsum += __shfl_xor_sync(0xFFFFFFFF, dsum, 4);
                dsum += __shfl_xor_sync(0xFFFFFFFF, dsum, 8);
                dsum += __shfl_xor_sync(0xFFFFFFFF, dsum, 16);
                psum += __shfl_xor_sync(0xFFFFFFFF, psum, 4);
                psum += __shfl_xor_sync(0xFFFFFFFF, psum, 8);
                psum += __shfl_xor_sync(0xFFFFFFFF, psum, 16);
                if ((lane >> 2) == 0) {
                    atomicAdd(&redDc[cloc], dsum);
                    atomicAdd(&redPc[cloc], psum);
                }
            }
        }
    }

    __syncthreads();
    if (tid < BM) {
        atomicAdd(&g_denom[row0 + tid], redD[tid]);
        atomicAdd(&g_pos[row0 + tid],   redP[tid]);
    } else if (offdiag && tid < BM + BN) {
        atomicAdd(&g_denom[col0 + tid - BM], redDc[tid - BM]);
        atomicAdd(&g_pos[col0 + tid - BM],   redPc[tid - BM]);
    }
}

// ---- finalize: label histogram, per-row combine, scalar loss ----
__global__ void finalize_kernel(const int* __restrict__ Lraw, float* __restrict__ out) {
    __shared__ int cnt[NCLS];
    __shared__ double red[256];
    __shared__ int s_is64;
    const int tid = threadIdx.x;

    if (tid == 0) s_is64 = detect_is64(Lraw);
    if (tid < NCLS) cnt[tid] = 0;
    __syncthreads();
    const int is64 = s_is64;

    for (int i = tid; i < N_ROWS; i += 256)
        atomicAdd(&cnt[get_label(Lraw, i, is64)], 1);
    __syncthreads();

    double acc = 0.0;
    for (int i = tid; i < N_ROWS; i += 256) {
        int P = cnt[get_label(Lraw, i, is64)] - 1;
        acc += (double)P * (2.0 + (double)logf(g_denom[i])) - (double)g_pos[i];
    }
    red[tid] = acc;
    __syncthreads();
    for (int s = 128; s > 0; s >>= 1) {
        if (tid < s) red[tid] += red[tid + s];
        __syncthreads();
    }
    if (tid == 0) {
        long long npos = 0;
        for (int c = 0; c < NCLS; c++)
            npos += (long long)cnt[c] * (long long)(cnt[c] - 1);
        out[0] = (float)(red[0] / (double)npos);
    }
}

extern "C" void kernel_launch(void* const* d_in, const int* in_sizes, int n_in,
                              void* d_out, int out_size) {
    const float* E    = (const float*)d_in[0];
    const int*   Lraw = (const int*)d_in[1];   // width auto-detected on device
    float* out = (float*)d_out;

    const int DYN_SMEM = 2 * 2 * 2 * BM * SSTRIDE;   // 2 stages * (A+B) bytes = 73728
    cudaFuncSetAttribute(sim_kernel, cudaFuncAttributeMaxDynamicSharedMemorySize, DYN_SMEM);

    prep_kernel<<<(N_ROWS * DIM / 4) / 256, 256>>>(E);
    sim_kernel<<<NTILES, 256, DYN_SMEM>>>(Lraw);
    finalize_kernel<<<1, 256>>>(Lraw, out);
}